// round 1
// baseline (speedup 1.0000x reference)
#include <cuda_runtime.h>
#include <math.h>

// MLA config (fixed by the problem)
#define BATCH 2
#define SEQ   2048
#define DIM   1024
#define HEADS 16
#define DHEAD 64
#define LATENT 256
#define ROWS  (BATCH*SEQ)        // 4096
#define SCALE 0.125f             // 64^-0.5

// ---------------------------------------------------------------------------
// Scratch (static __device__ arrays; no allocation allowed)
// ---------------------------------------------------------------------------
__device__ float g_q[ROWS * DIM];      // 16 MB
__device__ float g_lat[ROWS * LATENT]; //  4 MB
__device__ float g_k[ROWS * DIM];      // 16 MB
__device__ float g_v[ROWS * DIM];      // 16 MB
__device__ float g_att[ROWS * DIM];    // 16 MB

// ---------------------------------------------------------------------------
// Generic fp32 GEMM + bias: C[M,N] = A[M,K] @ B[K,N] + bias[N]
// 64x64 block tile, BK=16, 256 threads, 4x4 register microtile.
// M,N multiples of 64; K multiple of 16 (true for all call sites).
// ---------------------------------------------------------------------------
__global__ __launch_bounds__(256) void gemm_bias_kernel(
    const float* __restrict__ A, const float* __restrict__ Bm,
    const float* __restrict__ bias, float* __restrict__ C,
    int M, int N, int K)
{
    __shared__ float As[16][65];  // [k][m]
    __shared__ float Bs[16][65];  // [k][n]

    const int tx = threadIdx.x & 15;
    const int ty = threadIdx.x >> 4;
    const int row0 = blockIdx.y * 64;
    const int col0 = blockIdx.x * 64;

    float acc[4][4] = {};

    for (int k0 = 0; k0 < K; k0 += 16) {
        // Load A tile: 64 rows x 16 k. thread t -> row t/4, float4 t%4
        {
            int r = threadIdx.x >> 2;
            int f = threadIdx.x & 3;
            float4 a = *reinterpret_cast<const float4*>(&A[(size_t)(row0 + r) * K + k0 + f * 4]);
            As[f * 4 + 0][r] = a.x;
            As[f * 4 + 1][r] = a.y;
            As[f * 4 + 2][r] = a.z;
            As[f * 4 + 3][r] = a.w;
        }
        // Load B tile: 16 k rows x 64 n. thread t -> k t/16, float4 t%16
        {
            int kk = threadIdx.x >> 4;
            int f  = threadIdx.x & 15;
            float4 b = *reinterpret_cast<const float4*>(&Bm[(size_t)(k0 + kk) * N + col0 + f * 4]);
            Bs[kk][f * 4 + 0] = b.x;
            Bs[kk][f * 4 + 1] = b.y;
            Bs[kk][f * 4 + 2] = b.z;
            Bs[kk][f * 4 + 3] = b.w;
        }
        __syncthreads();

        #pragma unroll
        for (int kk = 0; kk < 16; kk++) {
            float a[4], b[4];
            #pragma unroll
            for (int i = 0; i < 4; i++) a[i] = As[kk][ty * 4 + i];
            #pragma unroll
            for (int j = 0; j < 4; j++) b[j] = Bs[kk][tx * 4 + j];
            #pragma unroll
            for (int i = 0; i < 4; i++)
                #pragma unroll
                for (int j = 0; j < 4; j++)
                    acc[i][j] = fmaf(a[i], b[j], acc[i][j]);
        }
        __syncthreads();
    }

    #pragma unroll
    for (int j = 0; j < 4; j++) {
        float bj = bias[col0 + tx * 4 + j];
        #pragma unroll
        for (int i = 0; i < 4; i++)
            C[(size_t)(row0 + ty * 4 + i) * N + col0 + tx * 4 + j] = acc[i][j] + bj;
    }
}

// ---------------------------------------------------------------------------
// Flash attention (fp32): grid (S/64, H, B), 256 threads
// q,k,v,o laid out [B*S, H*DHEAD]; per block: 64 queries x full head.
// ---------------------------------------------------------------------------
struct AttnSmem {
    float Qs[64][65];  // [query][dim]  (pre-scaled)
    float Ks[64][65];  // [key][dim]
    float Vs[64][65];  // [key][dim]
    float Ss[64][68];  // scores / probabilities
    float mrow[64];
    float lrow[64];
    float fac[64];
};

__global__ __launch_bounds__(256) void attn_kernel(
    const float* __restrict__ q, const float* __restrict__ k,
    const float* __restrict__ v, float* __restrict__ o)
{
    extern __shared__ char smem_raw[];
    AttnSmem& sm = *reinterpret_cast<AttnSmem*>(smem_raw);

    const int qb = blockIdx.x;
    const int h  = blockIdx.y;
    const int b  = blockIdx.z;
    const int tx = threadIdx.x & 15;
    const int ty = threadIdx.x >> 4;

    const float* qbase = q + ((size_t)(b * SEQ + qb * 64)) * DIM + h * DHEAD;

    // Load + pre-scale Q tile (64 x 64), 1024 float4 / 256 threads = 4 each
    #pragma unroll
    for (int it = 0; it < 4; it++) {
        int idx = it * 256 + threadIdx.x;
        int r = idx >> 4;
        int f = idx & 15;
        float4 a = *reinterpret_cast<const float4*>(&qbase[(size_t)r * DIM + f * 4]);
        sm.Qs[r][f * 4 + 0] = a.x * SCALE;
        sm.Qs[r][f * 4 + 1] = a.y * SCALE;
        sm.Qs[r][f * 4 + 2] = a.z * SCALE;
        sm.Qs[r][f * 4 + 3] = a.w * SCALE;
    }
    if (threadIdx.x < 64) {
        sm.mrow[threadIdx.x] = -1e30f;
        sm.lrow[threadIdx.x] = 0.0f;
    }

    float acc[4][4] = {};

    for (int kb = 0; kb < SEQ / 64; kb++) {
        const float* kbase = k + ((size_t)(b * SEQ + kb * 64)) * DIM + h * DHEAD;
        const float* vbase = v + ((size_t)(b * SEQ + kb * 64)) * DIM + h * DHEAD;

        #pragma unroll
        for (int it = 0; it < 4; it++) {
            int idx = it * 256 + threadIdx.x;
            int r = idx >> 4;
            int f = idx & 15;
            float4 a = *reinterpret_cast<const float4*>(&kbase[(size_t)r * DIM + f * 4]);
            sm.Ks[r][f * 4 + 0] = a.x;
            sm.Ks[r][f * 4 + 1] = a.y;
            sm.Ks[r][f * 4 + 2] = a.z;
            sm.Ks[r][f * 4 + 3] = a.w;
            float4 vv = *reinterpret_cast<const float4*>(&vbase[(size_t)r * DIM + f * 4]);
            sm.Vs[r][f * 4 + 0] = vv.x;
            sm.Vs[r][f * 4 + 1] = vv.y;
            sm.Vs[r][f * 4 + 2] = vv.z;
            sm.Vs[r][f * 4 + 3] = vv.w;
        }
        __syncthreads();

        // S = Q @ K^T  (64x64), 4x4 per thread
        float sacc[4][4] = {};
        #pragma unroll 8
        for (int kk = 0; kk < DHEAD; kk++) {
            float a[4], bb[4];
            #pragma unroll
            for (int i = 0; i < 4; i++) a[i]  = sm.Qs[ty * 4 + i][kk];
            #pragma unroll
            for (int j = 0; j < 4; j++) bb[j] = sm.Ks[tx * 4 + j][kk];
            #pragma unroll
            for (int i = 0; i < 4; i++)
                #pragma unroll
                for (int j = 0; j < 4; j++)
                    sacc[i][j] = fmaf(a[i], bb[j], sacc[i][j]);
        }
        #pragma unroll
        for (int i = 0; i < 4; i++)
            #pragma unroll
            for (int j = 0; j < 4; j++)
                sm.Ss[ty * 4 + i][tx * 4 + j] = sacc[i][j];
        __syncthreads();

        // Online softmax: 4 threads per row (16 cols each) + shuffles
        {
            int r  = threadIdx.x >> 2;
            int qd = threadIdx.x & 3;
            float mx = -1e30f;
            #pragma unroll
            for (int i = 0; i < 16; i++) mx = fmaxf(mx, sm.Ss[r][qd * 16 + i]);
            mx = fmaxf(mx, __shfl_xor_sync(0xffffffffu, mx, 1));
            mx = fmaxf(mx, __shfl_xor_sync(0xffffffffu, mx, 2));
            float newm = fmaxf(sm.mrow[r], mx);
            float sum = 0.0f;
            #pragma unroll
            for (int i = 0; i < 16; i++) {
                float p = __expf(sm.Ss[r][qd * 16 + i] - newm);
                sm.Ss[r][qd * 16 + i] = p;
                sum += p;
            }
            sum += __shfl_xor_sync(0xffffffffu, sum, 1);
            sum += __shfl_xor_sync(0xffffffffu, sum, 2);
            if (qd == 0) {
                float f = __expf(sm.mrow[r] - newm);
                sm.fac[r]  = f;
                sm.lrow[r] = sm.lrow[r] * f + sum;
                sm.mrow[r] = newm;
            }
        }
        __syncthreads();

        // O = O * fac + P @ V
        float frow[4];
        #pragma unroll
        for (int i = 0; i < 4; i++) frow[i] = sm.fac[ty * 4 + i];
        #pragma unroll
        for (int i = 0; i < 4; i++)
            #pragma unroll
            for (int j = 0; j < 4; j++)
                acc[i][j] *= frow[i];

        #pragma unroll 8
        for (int cc = 0; cc < 64; cc++) {
            float p[4], vv[4];
            #pragma unroll
            for (int i = 0; i < 4; i++) p[i]  = sm.Ss[ty * 4 + i][cc];
            #pragma unroll
            for (int j = 0; j < 4; j++) vv[j] = sm.Vs[cc][tx * 4 + j];
            #pragma unroll
            for (int i = 0; i < 4; i++)
                #pragma unroll
                for (int j = 0; j < 4; j++)
                    acc[i][j] = fmaf(p[i], vv[j], acc[i][j]);
        }
        __syncthreads();  // before next tile overwrites Ks/Vs/Ss
    }

    // Normalize and write
    #pragma unroll
    for (int i = 0; i < 4; i++) {
        float inv = 1.0f / sm.lrow[ty * 4 + i];
        #pragma unroll
        for (int j = 0; j < 4; j++) {
            size_t off = ((size_t)(b * SEQ + qb * 64 + ty * 4 + i)) * DIM + h * DHEAD + tx * 4 + j;
            o[off] = acc[i][j] * inv;
        }
    }
}

// ---------------------------------------------------------------------------
// Launch
// ---------------------------------------------------------------------------
extern "C" void kernel_launch(void* const* d_in, const int* in_sizes, int n_in,
                              void* d_out, int out_size)
{
    (void)in_sizes; (void)n_in; (void)out_size;
    const float* x  = (const float*)d_in[0];
    const float* Wq = (const float*)d_in[1];
    const float* bq = (const float*)d_in[2];
    const float* Wl = (const float*)d_in[3];
    const float* bl = (const float*)d_in[4];
    const float* Wk = (const float*)d_in[5];
    const float* bk = (const float*)d_in[6];
    const float* Wv = (const float*)d_in[7];
    const float* bv = (const float*)d_in[8];
    const float* Wo = (const float*)d_in[9];
    const float* bo = (const float*)d_in[10];
    float* out = (float*)d_out;

    float *qp, *latp, *kp, *vp, *attp;
    cudaGetSymbolAddress((void**)&qp,   g_q);
    cudaGetSymbolAddress((void**)&latp, g_lat);
    cudaGetSymbolAddress((void**)&kp,   g_k);
    cudaGetSymbolAddress((void**)&vp,   g_v);
    cudaGetSymbolAddress((void**)&attp, g_att);

    cudaFuncSetAttribute(attn_kernel,
                         cudaFuncAttributeMaxDynamicSharedMemorySize,
                         (int)sizeof(AttnSmem));

    dim3 blk(256);

    // q = x @ Wq + bq              [4096,1024]x[1024,1024]
    gemm_bias_kernel<<<dim3(DIM / 64, ROWS / 64), blk>>>(x, Wq, bq, qp, ROWS, DIM, DIM);
    // latent = x @ Wl + bl         [4096,1024]x[1024,256]
    gemm_bias_kernel<<<dim3(LATENT / 64, ROWS / 64), blk>>>(x, Wl, bl, latp, ROWS, LATENT, DIM);
    // k = latent @ Wk + bk         [4096,256]x[256,1024]
    gemm_bias_kernel<<<dim3(DIM / 64, ROWS / 64), blk>>>(latp, Wk, bk, kp, ROWS, DIM, LATENT);
    // v = latent @ Wv + bv
    gemm_bias_kernel<<<dim3(DIM / 64, ROWS / 64), blk>>>(latp, Wv, bv, vp, ROWS, DIM, LATENT);
    // attention
    attn_kernel<<<dim3(SEQ / 64, HEADS, BATCH), blk, sizeof(AttnSmem)>>>(qp, kp, vp, attp);
    // out = att @ Wo + bo
    gemm_bias_kernel<<<dim3(DIM / 64, ROWS / 64), blk>>>(attp, Wo, bo, out, ROWS, DIM, DIM);
}

// round 2
// speedup vs baseline: 1.2080x; 1.2080x over previous
#include <cuda_runtime.h>
#include <math.h>

// MLA config (fixed by the problem)
#define BATCH 2
#define SEQ   2048
#define DIM   1024
#define HEADS 16
#define DHEAD 64
#define LATENT 256
#define ROWS  (BATCH*SEQ)        // 4096
#define SCALE 0.125f             // 64^-0.5

typedef unsigned long long ull;

// ---------------------------------------------------------------------------
// f32x2 packed helpers (sm_103a FFMA2 path — only reachable via PTX)
// ---------------------------------------------------------------------------
__device__ __forceinline__ ull f2dup(float x) {
    ull r; asm("mov.b64 %0, {%1,%1};" : "=l"(r) : "f"(x)); return r;
}
__device__ __forceinline__ ull ffma2(ull a, ull b, ull c) {
    ull d; asm("fma.rn.f32x2 %0, %1, %2, %3;" : "=l"(d) : "l"(a), "l"(b), "l"(c)); return d;
}
__device__ __forceinline__ ull fmul2(ull a, ull b) {
    ull d; asm("mul.rn.f32x2 %0, %1, %2;" : "=l"(d) : "l"(a), "l"(b)); return d;
}
__device__ __forceinline__ float2 f2unpack(ull v) {
    float2 f; asm("mov.b64 {%0,%1}, %2;" : "=f"(f.x), "=f"(f.y) : "l"(v)); return f;
}

// ---------------------------------------------------------------------------
// Scratch (static __device__ arrays; no allocation allowed)
// ---------------------------------------------------------------------------
__device__ float g_q[ROWS * DIM];      // 16 MB
__device__ float g_lat[ROWS * LATENT]; //  4 MB
__device__ float g_k[ROWS * DIM];      // 16 MB
__device__ float g_v[ROWS * DIM];      // 16 MB
__device__ float g_att[ROWS * DIM];    // 16 MB

// ---------------------------------------------------------------------------
// GEMM + bias: C[M,N] = A[M,K] @ B[K,N] + bias[N]
// 128x128 tile, BK=8, 256 threads, 8x8 microtile with f32x2 packed FMA.
// M,N multiples of 128; K multiple of 8 (true at all call sites).
// ---------------------------------------------------------------------------
__global__ __launch_bounds__(256) void gemm_bias_kernel(
    const float* __restrict__ A, const float* __restrict__ Bm,
    const float* __restrict__ bias, float* __restrict__ C,
    int M, int N, int K)
{
    __shared__ float As[8][132];  // [k][m]  (transposed A tile)
    __shared__ float Bs[8][132];  // [k][n]

    const int t  = threadIdx.x;
    const int tx = t & 15;        // 8 cols each -> 128
    const int ty = t >> 4;        // 8 rows each -> 128
    const int row0 = blockIdx.y * 128;
    const int col0 = blockIdx.x * 128;

    ull acc[8][4];                // [row][col-pair]
    #pragma unroll
    for (int i = 0; i < 8; i++)
        #pragma unroll
        for (int j = 0; j < 4; j++) acc[i][j] = 0ull;

    const int ar = t >> 1;        // A load: row 0..127
    const int af = t & 1;         // float4 index along K
    const int bk = t >> 5;        // B load: k row 0..7
    const int bf = t & 31;        // float4 along N

    for (int k0 = 0; k0 < K; k0 += 8) {
        // A tile 128x8 -> transposed store (conflict-free, checked mod-32)
        {
            float4 a = *reinterpret_cast<const float4*>(&A[(size_t)(row0 + ar) * K + k0 + af * 4]);
            As[af * 4 + 0][ar] = a.x;
            As[af * 4 + 1][ar] = a.y;
            As[af * 4 + 2][ar] = a.z;
            As[af * 4 + 3][ar] = a.w;
        }
        // B tile 8x128 -> natural float4 store
        {
            float4 b = *reinterpret_cast<const float4*>(&Bm[(size_t)(k0 + bk) * N + col0 + bf * 4]);
            *reinterpret_cast<float4*>(&Bs[bk][bf * 4]) = b;
        }
        __syncthreads();

        #pragma unroll
        for (int kk = 0; kk < 8; kk++) {
            float4 a0 = *reinterpret_cast<const float4*>(&As[kk][ty * 8]);
            float4 a1 = *reinterpret_cast<const float4*>(&As[kk][ty * 8 + 4]);
            ulonglong2 b0 = *reinterpret_cast<const ulonglong2*>(&Bs[kk][tx * 8]);
            ulonglong2 b1 = *reinterpret_cast<const ulonglong2*>(&Bs[kk][tx * 8 + 4]);
            ull ad[8];
            ad[0] = f2dup(a0.x); ad[1] = f2dup(a0.y); ad[2] = f2dup(a0.z); ad[3] = f2dup(a0.w);
            ad[4] = f2dup(a1.x); ad[5] = f2dup(a1.y); ad[6] = f2dup(a1.z); ad[7] = f2dup(a1.w);
            #pragma unroll
            for (int i = 0; i < 8; i++) {
                acc[i][0] = ffma2(ad[i], b0.x, acc[i][0]);
                acc[i][1] = ffma2(ad[i], b0.y, acc[i][1]);
                acc[i][2] = ffma2(ad[i], b1.x, acc[i][2]);
                acc[i][3] = ffma2(ad[i], b1.y, acc[i][3]);
            }
        }
        __syncthreads();
    }

    // Epilogue: add bias, store float2 pairs
    #pragma unroll
    for (int j = 0; j < 4; j++) {
        int c = col0 + tx * 8 + j * 2;
        float b0 = bias[c], b1 = bias[c + 1];
        #pragma unroll
        for (int i = 0; i < 8; i++) {
            float2 v = f2unpack(acc[i][j]);
            float2 o; o.x = v.x + b0; o.y = v.y + b1;
            *reinterpret_cast<float2*>(&C[(size_t)(row0 + ty * 8 + i) * N + c]) = o;
        }
    }
}

// ---------------------------------------------------------------------------
// Flash attention fp32 (f32x2): grid (S/128, H, B), 128 threads.
// 128-query x 64-key tiles; Q,K transposed in smem; register softmax with
// 8-lane butterflies; P->smem consumed by the same warp (no extra sync).
// ---------------------------------------------------------------------------
struct ASmem {
    float Qst[64][132];  // [dim][query], pre-scaled
    float Kst[64][68];   // [dim][key]
    float Vs[64][68];    // [key][dim]
    float Ss[128][65];   // probabilities (pad 65 -> conflict-free PV loads)
    float mrow[128];
    float lrow[128];
};

__global__ __launch_bounds__(128) void attn_kernel(
    const float* __restrict__ q, const float* __restrict__ k,
    const float* __restrict__ v, float* __restrict__ o)
{
    extern __shared__ char smem_raw[];
    ASmem& sm = *reinterpret_cast<ASmem*>(smem_raw);

    const int t  = threadIdx.x;
    const int tx = t & 7;        // 8 cols each -> 64 keys / dims
    const int ty = t >> 3;       // 8 rows each -> 128 queries
    const int q0 = blockIdx.x * 128;
    const int h  = blockIdx.y;
    const int b  = blockIdx.z;

    // Load Q tile transposed (+pre-scale). Lanes = consecutive rows ->
    // conflict-free transposed STS; gmem uncoalesced but L2-absorbed.
    {
        const float* qrow = q + ((size_t)(b * SEQ + q0 + t)) * DIM + h * DHEAD;
        #pragma unroll
        for (int f = 0; f < 16; f++) {
            float4 a = *reinterpret_cast<const float4*>(&qrow[f * 4]);
            sm.Qst[f * 4 + 0][t] = a.x * SCALE;
            sm.Qst[f * 4 + 1][t] = a.y * SCALE;
            sm.Qst[f * 4 + 2][t] = a.z * SCALE;
            sm.Qst[f * 4 + 3][t] = a.w * SCALE;
        }
    }
    sm.mrow[t] = -1e30f;
    sm.lrow[t] = 0.0f;

    ull oacc[8][4];
    #pragma unroll
    for (int i = 0; i < 8; i++)
        #pragma unroll
        for (int j = 0; j < 4; j++) oacc[i][j] = 0ull;

    for (int kb = 0; kb < SEQ / 64; kb++) {
        __syncthreads();  // previous PV readers done with Vs; Qst/mrow visible

        // K tile transposed
        {
            int r  = t & 63;
            int fh = t >> 6;
            const float* krow = k + ((size_t)(b * SEQ + kb * 64 + r)) * DIM + h * DHEAD + fh * 32;
            #pragma unroll
            for (int ff = 0; ff < 8; ff++) {
                float4 a = *reinterpret_cast<const float4*>(&krow[ff * 4]);
                int d = fh * 32 + ff * 4;
                sm.Kst[d + 0][r] = a.x;
                sm.Kst[d + 1][r] = a.y;
                sm.Kst[d + 2][r] = a.z;
                sm.Kst[d + 3][r] = a.w;
            }
        }
        // V tile natural layout
        {
            const float* vbase = v + ((size_t)(b * SEQ + kb * 64)) * DIM + h * DHEAD;
            #pragma unroll
            for (int it = 0; it < 8; it++) {
                int idx = it * 128 + t;
                int r = idx >> 4, f = idx & 15;
                *reinterpret_cast<float4*>(&sm.Vs[r][f * 4]) =
                    *reinterpret_cast<const float4*>(&vbase[(size_t)r * DIM + f * 4]);
            }
        }
        __syncthreads();

        // ---- S = Q @ K^T (128x64), 8x8 per thread, f32x2 over key pairs ----
        ull sacc[8][4];
        #pragma unroll
        for (int i = 0; i < 8; i++)
            #pragma unroll
            for (int j = 0; j < 4; j++) sacc[i][j] = 0ull;

        #pragma unroll 8
        for (int kk = 0; kk < DHEAD; kk++) {
            float4 a0 = *reinterpret_cast<const float4*>(&sm.Qst[kk][ty * 8]);
            float4 a1 = *reinterpret_cast<const float4*>(&sm.Qst[kk][ty * 8 + 4]);
            ulonglong2 b0 = *reinterpret_cast<const ulonglong2*>(&sm.Kst[kk][tx * 8]);
            ulonglong2 b1 = *reinterpret_cast<const ulonglong2*>(&sm.Kst[kk][tx * 8 + 4]);
            ull ad[8];
            ad[0] = f2dup(a0.x); ad[1] = f2dup(a0.y); ad[2] = f2dup(a0.z); ad[3] = f2dup(a0.w);
            ad[4] = f2dup(a1.x); ad[5] = f2dup(a1.y); ad[6] = f2dup(a1.z); ad[7] = f2dup(a1.w);
            #pragma unroll
            for (int i = 0; i < 8; i++) {
                sacc[i][0] = ffma2(ad[i], b0.x, sacc[i][0]);
                sacc[i][1] = ffma2(ad[i], b0.y, sacc[i][1]);
                sacc[i][2] = ffma2(ad[i], b1.x, sacc[i][2]);
                sacc[i][3] = ffma2(ad[i], b1.y, sacc[i][3]);
            }
        }

        // ---- Online softmax, register-resident (8-lane butterflies) ----
        #pragma unroll
        for (int i = 0; i < 8; i++) {
            int r = ty * 8 + i;
            float2 p0 = f2unpack(sacc[i][0]);
            float2 p1 = f2unpack(sacc[i][1]);
            float2 p2 = f2unpack(sacc[i][2]);
            float2 p3 = f2unpack(sacc[i][3]);
            float s0 = p0.x, s1 = p0.y, s2 = p1.x, s3 = p1.y;
            float s4 = p2.x, s5 = p2.y, s6 = p3.x, s7 = p3.y;
            float mx = fmaxf(fmaxf(fmaxf(s0, s1), fmaxf(s2, s3)),
                             fmaxf(fmaxf(s4, s5), fmaxf(s6, s7)));
            mx = fmaxf(mx, __shfl_xor_sync(0xffffffffu, mx, 1));
            mx = fmaxf(mx, __shfl_xor_sync(0xffffffffu, mx, 2));
            mx = fmaxf(mx, __shfl_xor_sync(0xffffffffu, mx, 4));
            float mold = sm.mrow[r];
            float mnew = fmaxf(mold, mx);
            s0 = __expf(s0 - mnew); s1 = __expf(s1 - mnew);
            s2 = __expf(s2 - mnew); s3 = __expf(s3 - mnew);
            s4 = __expf(s4 - mnew); s5 = __expf(s5 - mnew);
            s6 = __expf(s6 - mnew); s7 = __expf(s7 - mnew);
            float sum = ((s0 + s1) + (s2 + s3)) + ((s4 + s5) + (s6 + s7));
            sum += __shfl_xor_sync(0xffffffffu, sum, 1);
            sum += __shfl_xor_sync(0xffffffffu, sum, 2);
            sum += __shfl_xor_sync(0xffffffffu, sum, 4);
            float fac = __expf(mold - mnew);
            if (tx == 0) {
                sm.mrow[r] = mnew;
                sm.lrow[r] = sm.lrow[r] * fac + sum;
            }
            ull fd = f2dup(fac);
            #pragma unroll
            for (int jp = 0; jp < 4; jp++) oacc[i][jp] = fmul2(oacc[i][jp], fd);
            int c = tx * 8;
            sm.Ss[r][c + 0] = s0; sm.Ss[r][c + 1] = s1;
            sm.Ss[r][c + 2] = s2; sm.Ss[r][c + 3] = s3;
            sm.Ss[r][c + 4] = s4; sm.Ss[r][c + 5] = s5;
            sm.Ss[r][c + 6] = s6; sm.Ss[r][c + 7] = s7;
        }
        // Ss rows needed below were written by this same warp -> no block sync.

        // ---- O += P @ V, 8 rows x 4 dim-pairs per thread ----
        #pragma unroll 4
        for (int j = 0; j < 64; j++) {
            ulonglong2 v0 = *reinterpret_cast<const ulonglong2*>(&sm.Vs[j][tx * 8]);
            ulonglong2 v1 = *reinterpret_cast<const ulonglong2*>(&sm.Vs[j][tx * 8 + 4]);
            #pragma unroll
            for (int i = 0; i < 8; i++) {
                ull pd = f2dup(sm.Ss[ty * 8 + i][j]);
                oacc[i][0] = ffma2(pd, v0.x, oacc[i][0]);
                oacc[i][1] = ffma2(pd, v0.y, oacc[i][1]);
                oacc[i][2] = ffma2(pd, v1.x, oacc[i][2]);
                oacc[i][3] = ffma2(pd, v1.y, oacc[i][3]);
            }
        }
    }

    // ---- Normalize and write ----
    #pragma unroll
    for (int i = 0; i < 8; i++) {
        int r = ty * 8 + i;
        float inv = 1.0f / sm.lrow[r];
        #pragma unroll
        for (int jp = 0; jp < 4; jp++) {
            float2 vv = f2unpack(oacc[i][jp]);
            float2 ov; ov.x = vv.x * inv; ov.y = vv.y * inv;
            size_t off = ((size_t)(b * SEQ + q0 + r)) * DIM + h * DHEAD + tx * 8 + jp * 2;
            *reinterpret_cast<float2*>(&o[off]) = ov;
        }
    }
}

// ---------------------------------------------------------------------------
// Launch
// ---------------------------------------------------------------------------
extern "C" void kernel_launch(void* const* d_in, const int* in_sizes, int n_in,
                              void* d_out, int out_size)
{
    (void)in_sizes; (void)n_in; (void)out_size;
    const float* x  = (const float*)d_in[0];
    const float* Wq = (const float*)d_in[1];
    const float* bq = (const float*)d_in[2];
    const float* Wl = (const float*)d_in[3];
    const float* bl = (const float*)d_in[4];
    const float* Wk = (const float*)d_in[5];
    const float* bk = (const float*)d_in[6];
    const float* Wv = (const float*)d_in[7];
    const float* bv = (const float*)d_in[8];
    const float* Wo = (const float*)d_in[9];
    const float* bo = (const float*)d_in[10];
    float* out = (float*)d_out;

    float *qp, *latp, *kp, *vp, *attp;
    cudaGetSymbolAddress((void**)&qp,   g_q);
    cudaGetSymbolAddress((void**)&latp, g_lat);
    cudaGetSymbolAddress((void**)&kp,   g_k);
    cudaGetSymbolAddress((void**)&vp,   g_v);
    cudaGetSymbolAddress((void**)&attp, g_att);

    cudaFuncSetAttribute(attn_kernel,
                         cudaFuncAttributeMaxDynamicSharedMemorySize,
                         (int)sizeof(ASmem));

    // q = x @ Wq + bq              [4096,1024]x[1024,1024]
    gemm_bias_kernel<<<dim3(DIM / 128, ROWS / 128), 256>>>(x, Wq, bq, qp, ROWS, DIM, DIM);
    // latent = x @ Wl + bl         [4096,1024]x[1024,256]
    gemm_bias_kernel<<<dim3(LATENT / 128, ROWS / 128), 256>>>(x, Wl, bl, latp, ROWS, LATENT, DIM);
    // k = latent @ Wk + bk         [4096,256]x[256,1024]
    gemm_bias_kernel<<<dim3(DIM / 128, ROWS / 128), 256>>>(latp, Wk, bk, kp, ROWS, DIM, LATENT);
    // v = latent @ Wv + bv
    gemm_bias_kernel<<<dim3(DIM / 128, ROWS / 128), 256>>>(latp, Wv, bv, vp, ROWS, DIM, LATENT);
    // attention
    attn_kernel<<<dim3(SEQ / 128, HEADS, BATCH), 128, sizeof(ASmem)>>>(qp, kp, vp, attp);
    // out = att @ Wo + bo
    gemm_bias_kernel<<<dim3(DIM / 128, ROWS / 128), 256>>>(attp, Wo, bo, out, ROWS, DIM, DIM);
}